// round 15
// baseline (speedup 1.0000x reference)
#include <cuda_runtime.h>
#include <cstdint>

// out(b, y, x) = bilinear sample of img_b at (y + 5 + py, x + 5 + px), zero
// outside [0, 522).
// 256-thread CTA = two 128-thread groups; each group produces 4 output rows
// x 512 px (4 consecutive px per thread, float4 everywhere). Per thread:
// 10 LDG.128 (front-batched, MLP=10) + 4 STG.128.
// Cache-policy steering: interior source rows (r=1..3, dead after this CTA)
// load evict-first (__ldcs); boundary rows (r=0 and r=4, re-read by the
// y-adjacent group/CTA) load with default policy so they stay L2-resident
// for the successor's request. Group 0's r=4 row == group 1's r=0 row
// (same CTA -> L1 hit); cross-CTA boundary rows ride L2.
// Column offset/weight hoisted (validated R6: rel_err ~1.2e-5). Row
// alignment: 522 % 4 == 2 -> source rows alternate shift M0 / (M0+2)&3;
// 2*(Y+4g)+X0 == 2Y+X0 (mod 4) so one uniform 4-way dispatch per CTA.
// Worst-case aligned-quad read ends exactly at the buffer's last element
// (521*522+9+508 -> 272483): no overrun.

static constexpr int NPAD = 522;
static constexpr int NOUT = 512;
static constexpr int B    = 256;

__device__ __forceinline__ float comp(const float4& A, const float4& Bq, int i) {
    switch (i) {
    case 0: return A.x;  case 1: return A.y;  case 2: return A.z;  case 3: return A.w;
    case 4: return Bq.x; case 5: return Bq.y; case 6: return Bq.z; default: return Bq.w;
    }
}

template <int M0>
__device__ __forceinline__ void fast_quad(
    const float* __restrict__ base, float* __restrict__ o0,
    int lane, int Y, int X0, float wx, const float* __restrict__ wy)
{
    const int c0 = Y * NPAD + X0 + 4 * lane;

    // 5 source rows, 2 aligned quads each. Boundary rows (0,4) default
    // policy (kept for reuse); interior rows (1..3) streaming (evict-first).
    float4 A[5], Bq[5];
    #pragma unroll
    for (int r = 0; r < 5; r++) {
        const int c = c0 + r * NPAD;
        const float4* q = reinterpret_cast<const float4*>(base + (c & ~3));
        if (r == 0 || r == 4) {
            A[r]  = __ldg(q);
            Bq[r] = __ldg(q + 1);
        } else {
            A[r]  = __ldcs(q);
            Bq[r] = __ldcs(q + 1);
        }
    }

    // Horizontal lerps: shift M0 for even source rows, (M0+2)&3 for odd.
    float t[5][4];
    #pragma unroll
    for (int r = 0; r < 5; r++) {
        const int M = (r & 1) ? ((M0 + 2) & 3) : M0;
        #pragma unroll
        for (int i = 0; i < 4; i++) {
            const float a  = comp(A[r], Bq[r], M + i);
            const float bb = comp(A[r], Bq[r], M + i + 1);
            t[r][i] = a + wx * (bb - a);
        }
    }

    // Vertical lerps + stores.
    #pragma unroll
    for (int r = 0; r < 4; r++) {
        float4 v;
        v.x = t[r][0] + wy[r] * (t[r + 1][0] - t[r][0]);
        v.y = t[r][1] + wy[r] * (t[r + 1][1] - t[r][1]);
        v.z = t[r][2] + wy[r] * (t[r + 1][2] - t[r][2]);
        v.w = t[r][3] + wy[r] * (t[r + 1][3] - t[r][3]);
        *reinterpret_cast<float4*>(o0 + (size_t)r * NOUT + 4 * lane) = v;
    }
}

__global__ __launch_bounds__(256) void extract_patches_kernel(
    const float* __restrict__ img,   // (B, 522, 522, 1)
    const float* __restrict__ pos,   // (B, 2)  [px, py]
    float* __restrict__ out)         // (B, 512, 512, 1)
{
    const int b    = blockIdx.z;
    const int g    = threadIdx.x >> 7;          // group 0/1 within CTA
    const int lane = threadIdx.x & 127;
    const int y0   = blockIdx.y * 8 + g * 4;    // first of this group's 4 rows

    const float px = __ldg(pos + 2 * b);
    const float py = __ldg(pos + 2 * b + 1);

    // Exact reference row arithmetic for this group's 4 output rows.
    float wy[4];
    int   Yr[4];
    #pragma unroll
    for (int r = 0; r < 4; r++) {
        const float sy = (float)(y0 + r + 5) + py;
        const float yf = floorf(sy);
        wy[r] = sy - yf;
        Yr[r] = (int)yf;
    }
    const int Y = Yr[0];

    const float s0  = 5.0f + px;
    const float x0f = floorf(s0);
    const float wx  = s0 - x0f;
    const int   X0  = (int)x0f;

    const float* base = img + (size_t)b * (NPAD * NPAD);
    float* o0 = out + ((size_t)b * NOUT + y0) * NOUT;

    const bool fast = (X0 >= 0) & (X0 <= 9) & (Y >= 0) & (Y <= NPAD - 5) &
                      (Yr[1] == Y + 1) & (Yr[2] == Y + 2) & (Yr[3] == Y + 3);

    if (fast) {
        const int m = (2 * Y + X0) & 3;   // uniform across the whole CTA
        switch (m) {
        case 0:  fast_quad<0>(base, o0, lane, Y, X0, wx, wy); break;
        case 1:  fast_quad<1>(base, o0, lane, Y, X0, wx, wy); break;
        case 2:  fast_quad<2>(base, o0, lane, Y, X0, wx, wy); break;
        default: fast_quad<3>(base, o0, lane, Y, X0, wx, wy); break;
        }
    } else {
        // Exact per-pixel path with full predication (handles zero fill).
        #pragma unroll
        for (int r = 0; r < 4; r++) {
            const int   yy   = y0 + r;
            const float sy   = (float)(yy + 5) + py;
            const float yf   = floorf(sy);
            const float wyp  = sy - yf;
            const int   Yi   = (int)yf;
            const bool vy0 = ((unsigned)Yi       < (unsigned)NPAD);
            const bool vy1 = ((unsigned)(Yi + 1) < (unsigned)NPAD);
            const float* rr = base + (ptrdiff_t)Yi * NPAD;
            float* orow = out + ((size_t)b * NOUT + yy) * NOUT;
            #pragma unroll
            for (int i = 0; i < 4; i++) {
                const int   x    = 4 * lane + i;
                const float sx   = (float)(x + 5) + px;
                const float xf   = floorf(sx);
                const float wxp  = sx - xf;
                const int   X    = (int)xf;
                const bool vx0 = ((unsigned)X       < (unsigned)NPAD);
                const bool vx1 = ((unsigned)(X + 1) < (unsigned)NPAD);
                const float* p0 = rr + X;
                float g00 = 0.0f, g01 = 0.0f, g10 = 0.0f, g11 = 0.0f;
                if (vy0 && vx0) g00 = __ldg(p0);
                if (vy0 && vx1) g01 = __ldg(p0 + 1);
                if (vy1 && vx0) g10 = __ldg(p0 + NPAD);
                if (vy1 && vx1) g11 = __ldg(p0 + NPAD + 1);
                const float top = g00 + wxp * (g01 - g00);
                const float bot = g10 + wxp * (g11 - g10);
                orow[x] = top + wyp * (bot - top);
            }
        }
    }
}

extern "C" void kernel_launch(void* const* d_in, const int* in_sizes, int n_in,
                              void* d_out, int out_size)
{
    const float* img = (const float*)d_in[0];   // padded_obj: 256*522*522*1 f32
    const float* pos = (const float*)d_in[1];   // positions:  256*2 f32
    float* out = (float*)d_out;                 // 256*512*512*1 f32

    dim3 block(256, 1, 1);
    dim3 grid(1, NOUT / 8, B);                  // (1, 64, 256)
    extract_patches_kernel<<<grid, block>>>(img, pos, out);
}

// round 16
// speedup vs baseline: 1.1693x; 1.1693x over previous
#include <cuda_runtime.h>
#include <cstdint>

// FINAL (reverted to R9, the proven best: 82.4 us bench, ~78 us kernel,
// DRAM ~80% of spec with traffic at the unique-byte floor — converged at the
// B300 mixed read/write HBM ceiling).
//
// out(b, y, x) = bilinear sample of img_b at (y + 5 + py, x + 5 + px), zero
// outside [0, 522).
// FOUR output rows per thread, 4 consecutive px each, float4 everywhere.
// Output rows y..y+3 need source rows Y..Y+4: 5 source-row quad pairs
// (10 LDG.128, front-batched, MLP=10, default cache policy — intra-CTA L1
// reuse between adjacent lanes/rows is load-bearing; .cs proved -17%) +
// 4 STG.128 per thread. Column offset/weight hoisted (validated: rel_err
// ~1.2e-5 vs 1e-3 tolerance). Row alignment: 522 % 4 == 2, so source rows
// alternate shift M0 / (M0+2)&3 — one uniform 4-way template dispatch, zero
// per-pixel integer work. Worst-case aligned-quad read ends exactly at the
// buffer's last element (521*522 + 9 + 508 -> quad end 272483): no overrun.

static constexpr int NPAD = 522;
static constexpr int NOUT = 512;
static constexpr int B    = 256;

__device__ __forceinline__ float comp(const float4& A, const float4& Bq, int i) {
    switch (i) {
    case 0: return A.x;  case 1: return A.y;  case 2: return A.z;  case 3: return A.w;
    case 4: return Bq.x; case 5: return Bq.y; case 6: return Bq.z; default: return Bq.w;
    }
}

template <int M0>
__device__ __forceinline__ void fast_quad(
    const float* __restrict__ base, float* __restrict__ o0,
    int tid, int Y, int X0, float wx, const float* __restrict__ wy)
{
    const int c0 = Y * NPAD + X0 + 4 * tid;

    // 5 source rows, 2 aligned quads each. All loads issued up front (MLP=10).
    float4 A[5], Bq[5];
    #pragma unroll
    for (int r = 0; r < 5; r++) {
        const int c = c0 + r * NPAD;
        const float4* q = reinterpret_cast<const float4*>(base + (c & ~3));
        A[r]  = __ldg(q);
        Bq[r] = __ldg(q + 1);
    }

    // Horizontal lerps: t[r][i] for taps [c+i, c+i+1], shift M0 for even
    // source rows, (M0+2)&3 for odd (522 % 4 == 2).
    float t[5][4];
    #pragma unroll
    for (int r = 0; r < 5; r++) {
        const int M = (r & 1) ? ((M0 + 2) & 3) : M0;
        #pragma unroll
        for (int i = 0; i < 4; i++) {
            const float a  = comp(A[r], Bq[r], M + i);
            const float bb = comp(A[r], Bq[r], M + i + 1);
            t[r][i] = a + wx * (bb - a);
        }
    }

    // Vertical lerps + stores.
    #pragma unroll
    for (int r = 0; r < 4; r++) {
        float4 v;
        v.x = t[r][0] + wy[r] * (t[r + 1][0] - t[r][0]);
        v.y = t[r][1] + wy[r] * (t[r + 1][1] - t[r][1]);
        v.z = t[r][2] + wy[r] * (t[r + 1][2] - t[r][2]);
        v.w = t[r][3] + wy[r] * (t[r + 1][3] - t[r][3]);
        *reinterpret_cast<float4*>(o0 + (size_t)r * NOUT + 4 * tid) = v;
    }
}

__global__ __launch_bounds__(128) void extract_patches_kernel(
    const float* __restrict__ img,   // (B, 522, 522, 1)
    const float* __restrict__ pos,   // (B, 2)  [px, py]
    float* __restrict__ out)         // (B, 512, 512, 1)
{
    const int b   = blockIdx.z;
    const int y0  = blockIdx.y * 4;
    const int tid = threadIdx.x;

    const float px = __ldg(pos + 2 * b);
    const float py = __ldg(pos + 2 * b + 1);

    // Exact reference row arithmetic for all 4 output rows.
    float wy[4];
    int   Yr[4];
    #pragma unroll
    for (int r = 0; r < 4; r++) {
        const float sy = (float)(y0 + r + 5) + py;
        const float yf = floorf(sy);
        wy[r] = sy - yf;
        Yr[r] = (int)yf;
    }
    const int Y = Yr[0];

    const float s0  = 5.0f + px;
    const float x0f = floorf(s0);
    const float wx  = s0 - x0f;
    const int   X0  = (int)x0f;

    const float* base = img + (size_t)b * (NPAD * NPAD);
    float* o0 = out + ((size_t)b * NOUT + y0) * NOUT;

    const bool fast = (X0 >= 0) & (X0 <= 9) & (Y >= 0) & (Y <= NPAD - 5) &
                      (Yr[1] == Y + 1) & (Yr[2] == Y + 2) & (Yr[3] == Y + 3);

    if (fast) {
        const int m = (2 * Y + X0) & 3;   // uniform across block (4*tid % 4 == 0)
        switch (m) {
        case 0:  fast_quad<0>(base, o0, tid, Y, X0, wx, wy); break;
        case 1:  fast_quad<1>(base, o0, tid, Y, X0, wx, wy); break;
        case 2:  fast_quad<2>(base, o0, tid, Y, X0, wx, wy); break;
        default: fast_quad<3>(base, o0, tid, Y, X0, wx, wy); break;
        }
    } else {
        // Exact per-pixel path with full predication (handles zero fill).
        #pragma unroll
        for (int r = 0; r < 4; r++) {
            const int   yy   = y0 + r;
            const float sy   = (float)(yy + 5) + py;
            const float yf   = floorf(sy);
            const float wyp  = sy - yf;
            const int   Yi   = (int)yf;
            const bool vy0 = ((unsigned)Yi       < (unsigned)NPAD);
            const bool vy1 = ((unsigned)(Yi + 1) < (unsigned)NPAD);
            const float* rr = base + (ptrdiff_t)Yi * NPAD;
            float* orow = out + ((size_t)b * NOUT + yy) * NOUT;
            #pragma unroll
            for (int i = 0; i < 4; i++) {
                const int   x    = 4 * tid + i;
                const float sx   = (float)(x + 5) + px;
                const float xf   = floorf(sx);
                const float wxp  = sx - xf;
                const int   X    = (int)xf;
                const bool vx0 = ((unsigned)X       < (unsigned)NPAD);
                const bool vx1 = ((unsigned)(X + 1) < (unsigned)NPAD);
                const float* p0 = rr + X;
                float g00 = 0.0f, g01 = 0.0f, g10 = 0.0f, g11 = 0.0f;
                if (vy0 && vx0) g00 = __ldg(p0);
                if (vy0 && vx1) g01 = __ldg(p0 + 1);
                if (vy1 && vx0) g10 = __ldg(p0 + NPAD);
                if (vy1 && vx1) g11 = __ldg(p0 + NPAD + 1);
                const float top = g00 + wxp * (g01 - g00);
                const float bot = g10 + wxp * (g11 - g10);
                orow[x] = top + wyp * (bot - top);
            }
        }
    }
}

extern "C" void kernel_launch(void* const* d_in, const int* in_sizes, int n_in,
                              void* d_out, int out_size)
{
    const float* img = (const float*)d_in[0];   // padded_obj: 256*522*522*1 f32
    const float* pos = (const float*)d_in[1];   // positions:  256*2 f32
    float* out = (float*)d_out;                 // 256*512*512*1 f32

    dim3 block(128, 1, 1);
    dim3 grid(1, NOUT / 4, B);                  // (1, 128, 256)
    extract_patches_kernel<<<grid, block>>>(img, pos, out);
}

// round 17
// speedup vs baseline: 1.1711x; 1.0016x over previous
#include <cuda_runtime.h>
#include <cstdint>

// FINAL — converged at the B300 mixed read/write HBM ceiling.
// Best measured: 82.4 us bench / 78.2 us kernel, DRAM ~79% of 8 TB/s spec
// (~6.3 TB/s achieved), traffic at the unique-byte floor (~491 MB).
// Verified reproducible across two independent benches (R9, R16).
//
// out(b, y, x) = bilinear sample of img_b at (y + 5 + py, x + 5 + px), zero
// outside [0, 522).
// FOUR output rows per thread, 4 consecutive px each, float4 everywhere.
// Output rows y..y+3 need source rows Y..Y+4: 5 source-row quad pairs
// (10 LDG.128, front-batched, MLP=10, default cache policy — intra-CTA L1
// reuse between adjacent lanes/rows is load-bearing; .cs measured -17%) +
// 4 STG.128 per thread. Column offset/weight hoisted: X(x) = x + floor(5+px),
// wx = frac(5+px); deviation from the reference's per-pixel floor is
// <= ~1.6e-5 px -> rel_err 1.174e-5 vs 1e-3 tolerance. Row alignment:
// 522 % 4 == 2, so source rows alternate shift M0 / (M0+2)&3 — one uniform
// 4-way template dispatch, zero per-pixel integer work. Worst-case aligned
// quad read ends exactly at the buffer's last element (521*522 + 9 + 508 ->
// quad end 272483): no overrun. Rare rows (|offset| >= ~5 or floor
// inconsistency) take the exact per-pixel predicated path (zero fill).

static constexpr int NPAD = 522;
static constexpr int NOUT = 512;
static constexpr int B    = 256;

__device__ __forceinline__ float comp(const float4& A, const float4& Bq, int i) {
    switch (i) {
    case 0: return A.x;  case 1: return A.y;  case 2: return A.z;  case 3: return A.w;
    case 4: return Bq.x; case 5: return Bq.y; case 6: return Bq.z; default: return Bq.w;
    }
}

template <int M0>
__device__ __forceinline__ void fast_quad(
    const float* __restrict__ base, float* __restrict__ o0,
    int tid, int Y, int X0, float wx, const float* __restrict__ wy)
{
    const int c0 = Y * NPAD + X0 + 4 * tid;

    // 5 source rows, 2 aligned quads each. All loads issued up front (MLP=10).
    float4 A[5], Bq[5];
    #pragma unroll
    for (int r = 0; r < 5; r++) {
        const int c = c0 + r * NPAD;
        const float4* q = reinterpret_cast<const float4*>(base + (c & ~3));
        A[r]  = __ldg(q);
        Bq[r] = __ldg(q + 1);
    }

    // Horizontal lerps: t[r][i] for taps [c+i, c+i+1], shift M0 for even
    // source rows, (M0+2)&3 for odd (522 % 4 == 2).
    float t[5][4];
    #pragma unroll
    for (int r = 0; r < 5; r++) {
        const int M = (r & 1) ? ((M0 + 2) & 3) : M0;
        #pragma unroll
        for (int i = 0; i < 4; i++) {
            const float a  = comp(A[r], Bq[r], M + i);
            const float bb = comp(A[r], Bq[r], M + i + 1);
            t[r][i] = a + wx * (bb - a);
        }
    }

    // Vertical lerps + stores.
    #pragma unroll
    for (int r = 0; r < 4; r++) {
        float4 v;
        v.x = t[r][0] + wy[r] * (t[r + 1][0] - t[r][0]);
        v.y = t[r][1] + wy[r] * (t[r + 1][1] - t[r][1]);
        v.z = t[r][2] + wy[r] * (t[r + 1][2] - t[r][2]);
        v.w = t[r][3] + wy[r] * (t[r + 1][3] - t[r][3]);
        *reinterpret_cast<float4*>(o0 + (size_t)r * NOUT + 4 * tid) = v;
    }
}

__global__ __launch_bounds__(128) void extract_patches_kernel(
    const float* __restrict__ img,   // (B, 522, 522, 1)
    const float* __restrict__ pos,   // (B, 2)  [px, py]
    float* __restrict__ out)         // (B, 512, 512, 1)
{
    const int b   = blockIdx.z;
    const int y0  = blockIdx.y * 4;
    const int tid = threadIdx.x;

    const float px = __ldg(pos + 2 * b);
    const float py = __ldg(pos + 2 * b + 1);

    // Exact reference row arithmetic for all 4 output rows.
    float wy[4];
    int   Yr[4];
    #pragma unroll
    for (int r = 0; r < 4; r++) {
        const float sy = (float)(y0 + r + 5) + py;
        const float yf = floorf(sy);
        wy[r] = sy - yf;
        Yr[r] = (int)yf;
    }
    const int Y = Yr[0];

    const float s0  = 5.0f + px;
    const float x0f = floorf(s0);
    const float wx  = s0 - x0f;
    const int   X0  = (int)x0f;

    const float* base = img + (size_t)b * (NPAD * NPAD);
    float* o0 = out + ((size_t)b * NOUT + y0) * NOUT;

    const bool fast = (X0 >= 0) & (X0 <= 9) & (Y >= 0) & (Y <= NPAD - 5) &
                      (Yr[1] == Y + 1) & (Yr[2] == Y + 2) & (Yr[3] == Y + 3);

    if (fast) {
        const int m = (2 * Y + X0) & 3;   // uniform across block (4*tid % 4 == 0)
        switch (m) {
        case 0:  fast_quad<0>(base, o0, tid, Y, X0, wx, wy); break;
        case 1:  fast_quad<1>(base, o0, tid, Y, X0, wx, wy); break;
        case 2:  fast_quad<2>(base, o0, tid, Y, X0, wx, wy); break;
        default: fast_quad<3>(base, o0, tid, Y, X0, wx, wy); break;
        }
    } else {
        // Exact per-pixel path with full predication (handles zero fill).
        #pragma unroll
        for (int r = 0; r < 4; r++) {
            const int   yy   = y0 + r;
            const float sy   = (float)(yy + 5) + py;
            const float yf   = floorf(sy);
            const float wyp  = sy - yf;
            const int   Yi   = (int)yf;
            const bool vy0 = ((unsigned)Yi       < (unsigned)NPAD);
            const bool vy1 = ((unsigned)(Yi + 1) < (unsigned)NPAD);
            const float* rr = base + (ptrdiff_t)Yi * NPAD;
            float* orow = out + ((size_t)b * NOUT + yy) * NOUT;
            #pragma unroll
            for (int i = 0; i < 4; i++) {
                const int   x    = 4 * tid + i;
                const float sx   = (float)(x + 5) + px;
                const float xf   = floorf(sx);
                const float wxp  = sx - xf;
                const int   X    = (int)xf;
                const bool vx0 = ((unsigned)X       < (unsigned)NPAD);
                const bool vx1 = ((unsigned)(X + 1) < (unsigned)NPAD);
                const float* p0 = rr + X;
                float g00 = 0.0f, g01 = 0.0f, g10 = 0.0f, g11 = 0.0f;
                if (vy0 && vx0) g00 = __ldg(p0);
                if (vy0 && vx1) g01 = __ldg(p0 + 1);
                if (vy1 && vx0) g10 = __ldg(p0 + NPAD);
                if (vy1 && vx1) g11 = __ldg(p0 + NPAD + 1);
                const float top = g00 + wxp * (g01 - g00);
                const float bot = g10 + wxp * (g11 - g10);
                orow[x] = top + wyp * (bot - top);
            }
        }
    }
}

extern "C" void kernel_launch(void* const* d_in, const int* in_sizes, int n_in,
                              void* d_out, int out_size)
{
    const float* img = (const float*)d_in[0];   // padded_obj: 256*522*522*1 f32
    const float* pos = (const float*)d_in[1];   // positions:  256*2 f32
    float* out = (float*)d_out;                 // 256*512*512*1 f32

    dim3 block(128, 1, 1);
    dim3 grid(1, NOUT / 4, B);                  // (1, 128, 256)
    extract_patches_kernel<<<grid, block>>>(img, pos, out);
}